// round 10
// baseline (speedup 1.0000x reference)
#include <cuda_runtime.h>
#include <cstdint>

// ---------------------------------------------------------------------------
// out = ((x @ (w1_q*s1)) @ (w2_q*s2)) per expert.  E=8, T=4096, H=2048.
// Exact 16-bit activation split (hi,lo int8 planes).
// MIXED-DUTY WARPS, FINE INTERLEAVE: every warp runs an IMMA stream (hi
// plane) and a dp4a stream (lo plane), interleaved per-ks so both pipes are
// fed by all 16 warps at once (R2: tensor hits 96% with 4 feeders/SMSP;
// R8: dp4a hits its 2/cyc ceiling with 4 feeders/SMSP).
// Block tile 128x64 to keep 32 accs/thread. Bulk-copy loader (R9).
// out = (256*acc_hi + acc_lo) * s_row * wscale_col.
// ---------------------------------------------------------------------------

#define EE 8
#define TT 4096
#define HH 2048

#define BM 128
#define BN 64
#define BK 128
#define NKIT (HH / BK)          // 16
#define APLANE 16384            // 128x128 s8 tile
#define BPLANE 8192             // 64x128 s8 tile
#define STAGE (2 * APLANE + BPLANE)   // 40960
#define OFF_ALO APLANE
#define OFF_B   (2 * APLANE)
#define NSTAGE 4
#define DYNSMEM (NSTAGE * STAGE)      // 163840
#define XPITCH 68               // padded pitch for lo-acc exchange

// -------------------- scratch (tiled, pre-swizzled) ------------------------
// weights: [e][nb(32)][kb(16)][64x128]   activations: [e][mb(32)][kb(16)][128x128]
__device__ int8_t g_w1t[(size_t)EE * HH * HH];
__device__ int8_t g_w2t[(size_t)EE * HH * HH];
__device__ int8_t g_ahi[(size_t)EE * TT * HH];
__device__ int8_t g_alo[(size_t)EE * TT * HH];
__device__ float  g_rs [(size_t)EE * TT];
__device__ float  g_h  [(size_t)EE * TT * HH];   // layer-1 output fp32 (row-major)

// -------------------- helpers --------------------------------------------
__device__ __forceinline__ uint32_t smem_u32(const void* p) {
    uint32_t a;
    asm("{ .reg .u64 t; cvta.to.shared.u64 t, %1; cvt.u32.u64 %0, t; }"
        : "=r"(a) : "l"(p));
    return a;
}

#define MBARRIER_INIT(mbar, cnt) \
    asm volatile("mbarrier.init.shared.b64 [%0], %1;" \
                 :: "r"((uint32_t)(mbar)), "r"((uint32_t)(cnt)) : "memory")
#define MBARRIER_EXPECT_TX(mbar, tx) \
    asm volatile("mbarrier.arrive.expect_tx.shared.b64 _, [%0], %1;" \
                 :: "r"((uint32_t)(mbar)), "r"((uint32_t)(tx)) : "memory")

#define MBARRIER_WAIT_PARITY(mbar, par) do {                                   \
    uint32_t _m = (uint32_t)(mbar);                                            \
    uint32_t _p = (uint32_t)(par);                                             \
    uint32_t _done;                                                            \
    asm volatile("{\n\t.reg .pred p;\n\t"                                      \
        "mbarrier.try_wait.parity.shared.b64 p, [%1], %2;\n\t"                 \
        "selp.b32 %0, 1, 0, p;\n\t}"                                           \
        : "=r"(_done) : "r"(_m), "r"(_p) : "memory");                          \
    if (!_done) {                                                              \
        asm volatile("{\n\t.reg .pred P1;\n\t"                                 \
            "WL_%=:\n\t"                                                       \
            "mbarrier.try_wait.parity.shared.b64 P1, [%0], %1;\n\t"            \
            "@P1 bra.uni WD_%=;\n\t"                                           \
            "bra.uni WL_%=;\n\t"                                               \
            "WD_%=:\n\t}"                                                      \
            :: "r"(_m), "r"(_p) : "memory");                                   \
    }                                                                          \
} while (0)

#define CP_BULK(dst, src, nbytes, mbar) \
    asm volatile( \
        "cp.async.bulk.shared::cluster.global.mbarrier::complete_tx::bytes " \
        "[%0], [%1], %2, [%3];" \
        :: "r"((uint32_t)(dst)), "l"(src), "r"((uint32_t)(nbytes)), \
           "r"((uint32_t)(mbar)) : "memory")

__device__ __forceinline__ void imma(int* d, const uint32_t* a,
                                     const uint32_t* b) {
    asm volatile(
        "mma.sync.aligned.m16n8k32.row.col.s32.s8.s8.s32 "
        "{%0,%1,%2,%3},{%4,%5,%6,%7},{%8,%9},{%0,%1,%2,%3};"
        : "+r"(d[0]), "+r"(d[1]), "+r"(d[2]), "+r"(d[3])
        : "r"(a[0]), "r"(a[1]), "r"(a[2]), "r"(a[3]),
          "r"(b[0]), "r"(b[1]));
}

__device__ __forceinline__ int dp4a_(int a, int b, int c) {
    int d;
    asm("dp4a.s32.s32 %0, %1, %2, %3;" : "=r"(d) : "r"(a), "r"(b), "r"(c));
    return d;
}

// -------------------- weight convert + transpose + tile + swizzle ----------
// W int32 [E][k][n] -> tiles [e][nb(32)][kb(16)][64x128] int8, chunk-swizzled
__global__ void convw_kernel(const int* __restrict__ W,
                             int8_t* __restrict__ O) {
    __shared__ int8_t tile[32][33];
    const int e  = blockIdx.z;
    const int n0 = blockIdx.x * 32;
    const int k0 = blockIdx.y * 32;
    const int tx = threadIdx.x, ty = threadIdx.y;

    const int* src = W + ((size_t)e * HH + k0) * HH + n0;
#pragma unroll
    for (int r = 0; r < 4; r++) {
        tile[ty + r * 8][tx] = (int8_t)src[(size_t)(ty + r * 8) * HH + tx];
    }
    __syncthreads();
    const int t  = ty * 32 + tx;
    const int nr = t >> 3;              // 0..31
    const int c4 = (t & 7) * 4;         // 0..28
    uint32_t p = (uint32_t)(uint8_t)tile[c4 + 0][nr]
               | ((uint32_t)(uint8_t)tile[c4 + 1][nr] << 8)
               | ((uint32_t)(uint8_t)tile[c4 + 2][nr] << 16)
               | ((uint32_t)(uint8_t)tile[c4 + 3][nr] << 24);
    const int ng = n0 + nr;
    const int nb = ng >> 6, rowT = ng & 63;
    const int kin = (k0 & 127) + c4;
    const int ch  = kin >> 4;
    const uint32_t sw = (uint32_t)(((ch ^ (rowT & 7)) & 7) << 4) + (kin & 15);
    int8_t* dst = O + (((size_t)(e * 32 + nb) * 16 + (k0 >> 7)) << 13)
                    + rowT * 128 + sw;
    *(uint32_t*)dst = p;
}

// -------------------- activation quantize (tiled + swizzled output) --------
__global__ void quant_kernel(const float* __restrict__ X,
                             int8_t* __restrict__ Qh,
                             int8_t* __restrict__ Ql,
                             float* __restrict__ RS) {
    const int row = blockIdx.x;          // 0 .. EE*TT-1
    const float* x = X + (size_t)row * HH;
    const int t = threadIdx.x;           // 0..127

    float4 v[4];
#pragma unroll
    for (int j = 0; j < 4; j++) v[j] = ((const float4*)x)[t * 4 + j];

    float m = 0.0f;
#pragma unroll
    for (int j = 0; j < 4; j++) {
        m = fmaxf(m, fabsf(v[j].x)); m = fmaxf(m, fabsf(v[j].y));
        m = fmaxf(m, fabsf(v[j].z)); m = fmaxf(m, fabsf(v[j].w));
    }
#pragma unroll
    for (int o = 16; o; o >>= 1)
        m = fmaxf(m, __shfl_xor_sync(0xFFFFFFFFu, m, o));
    __shared__ float wr[4];
    if ((t & 31) == 0) wr[t >> 5] = m;
    __syncthreads();
    float mx = fmaxf(fmaxf(wr[0], wr[1]), fmaxf(wr[2], wr[3]));
    mx = fmaxf(mx, 1e-20f);
    const float inv = 32600.0f / mx;

    uint32_t hw[4], lw[4];
#pragma unroll
    for (int j = 0; j < 4; j++) {
        const int q0 = __float2int_rn(v[j].x * inv);
        const int q1 = __float2int_rn(v[j].y * inv);
        const int q2 = __float2int_rn(v[j].z * inv);
        const int q3 = __float2int_rn(v[j].w * inv);
        const int h0 = (q0 + 128) >> 8, h1 = (q1 + 128) >> 8;
        const int h2 = (q2 + 128) >> 8, h3 = (q3 + 128) >> 8;
        const int l0 = q0 - (h0 << 8), l1 = q1 - (h1 << 8);
        const int l2 = q2 - (h2 << 8), l3 = q3 - (h3 << 8);
        hw[j] = (h0 & 255) | ((h1 & 255) << 8) | ((h2 & 255) << 16)
              | ((uint32_t)(h3 & 255) << 24);
        lw[j] = (l0 & 255) | ((l1 & 255) << 8) | ((l2 & 255) << 16)
              | ((uint32_t)(l3 & 255) << 24);
    }

    const int e  = row >> 12;
    const int mm = row & 4095;
    const int kb = t >> 3;               // 0..15
    const int ch = t & 7;
    const int rowT = mm & 127;
    const uint32_t sw = (uint32_t)(((ch ^ (rowT & 7)) & 7) << 4);
    const size_t base = (((size_t)(e * 32 + (mm >> 7)) * 16 + kb) << 14)
                      + rowT * 128 + sw;
    *(int4*)(Qh + base) = make_int4(hw[0], hw[1], hw[2], hw[3]);
    *(int4*)(Ql + base) = make_int4(lw[0], lw[1], lw[2], lw[3]);
    if (t == 0) RS[row] = mx / 32600.0f;
}

// -------------------- mixed-duty interleaved GEMM --------------------------
__global__ void __launch_bounds__(512, 1)
mix_gemm(const int8_t* __restrict__ Ah, const int8_t* __restrict__ Al,
         const float* __restrict__ rs, const int8_t* __restrict__ Bt,
         const float* __restrict__ cs, float* __restrict__ C) {
    extern __shared__ __align__(128) char sm[];
    __shared__ __align__(8) uint64_t mbar_s[NSTAGE];
    const uint32_t sbase = smem_u32(sm);
    const uint32_t mb0 = smem_u32(mbar_s);
    const int tid = threadIdx.x;
    const int lane = tid & 31, wid = tid >> 5;

    const int e  = blockIdx.z;
    const int mb = blockIdx.y;           // 0..31
    const int nb = blockIdx.x;           // 0..31

    const int8_t* hiB = Ah + (((size_t)(e * 32 + mb) * 16) << 14);
    const int8_t* loB = Al + (((size_t)(e * 32 + mb) * 16) << 14);
    const int8_t* bB  = Bt + (((size_t)(e * 32 + nb) * 16) << 13);

    // warp region (both planes): rows r0 = (wid&7)*16, cols c0 = (wid>>3)*32
    const int r0 = (wid & 7) * 16;
    const int c0 = (wid >> 3) * 32;

    // ---- IMMA stream config (hi plane) ----
    const int grp = lane >> 2;
    const int tg4 = (lane & 3) * 4;
    const uint32_t baseA0 = (uint32_t)((r0 + grp) * 128 + tg4);
    const uint32_t baseA1 = (uint32_t)((r0 + 8 + grp) * 128 + tg4);
    uint32_t baseB[4];
#pragma unroll
    for (int nt = 0; nt < 4; nt++)
        baseB[nt] = (uint32_t)((c0 + nt * 8 + grp) * 128 + tg4);

    // ---- dp4a stream config (lo plane) ----
    const int lg = lane & 3;
    const int lh = lane >> 2;
    const uint32_t dpA0 = (uint32_t)((r0 + lg) * 128);
    const uint32_t dpB0 = (uint32_t)((c0 + lh) * 128);

    int acc_h[4][4];                    // hi: 4 n-tiles x 4 regs
    int acc_l[4][4];                    // lo: 4 rows x 4 cols
#pragma unroll
    for (int a = 0; a < 4; a++)
#pragma unroll
        for (int b = 0; b < 4; b++) { acc_h[a][b] = 0; acc_l[a][b] = 0; }

    if (tid == 0) {
#pragma unroll
        for (int s = 0; s < NSTAGE; s++) MBARRIER_INIT(mb0 + 8 * s, 1);
    }
    __syncthreads();

    if (tid == 0) {
#pragma unroll
        for (int p = 0; p < NSTAGE; p++) {
            const uint32_t st = sbase + p * STAGE;
            MBARRIER_EXPECT_TX(mb0 + 8 * p, STAGE);
            CP_BULK(st,           hiB + ((size_t)p << 14), APLANE, mb0 + 8 * p);
            CP_BULK(st + OFF_ALO, loB + ((size_t)p << 14), APLANE, mb0 + 8 * p);
            CP_BULK(st + OFF_B,   bB  + ((size_t)p << 13), BPLANE, mb0 + 8 * p);
        }
    }

#pragma unroll 1
    for (int i = 0; i < NKIT; i++) {
        const int s = i & 3;
        MBARRIER_WAIT_PARITY(mb0 + 8 * s, (i >> 2) & 1);

        const char* stA = sm + s * STAGE;
        const char* stL = stA + OFF_ALO;
        const char* stB = stA + OFF_B;

#pragma unroll
        for (int ks = 0; ks < 4; ks++) {
            // ---------- IMMA chunk (hi plane, k = ks*32..ks*32+31) ----------
            {
                const uint32_t xa = (uint32_t)((((2 * ks) ^ grp) & 7) << 4);
                const uint32_t xb = (uint32_t)((((2 * ks + 1) ^ grp) & 7) << 4);
                uint32_t ah[4];
                ah[0] = *(const uint32_t*)(stA + baseA0 + xa);
                ah[1] = *(const uint32_t*)(stA + baseA1 + xa);
                ah[2] = *(const uint32_t*)(stA + baseA0 + xb);
                ah[3] = *(const uint32_t*)(stA + baseA1 + xb);
#pragma unroll
                for (int nt = 0; nt < 4; nt++) {
                    uint32_t bf[2];
                    bf[0] = *(const uint32_t*)(stB + baseB[nt] + xa);
                    bf[1] = *(const uint32_t*)(stB + baseB[nt] + xb);
                    imma(acc_h[nt], ah, bf);
                }
            }
            // ---------- dp4a chunks (lo plane, same 32 k-values) ----------
#pragma unroll
            for (int h = 0; h < 2; h++) {
                const int kb = ks * 32 + h * 16;
                const uint32_t cA0 =
                    (uint32_t)(((((kb >> 4)) ^ lg) & 7) << 4);
                const uint32_t cA1 = cA0 ^ 64u;
                const uint32_t cB =
                    (uint32_t)(((((kb >> 4)) ^ lh) & 7) << 4);
                int4 bv[4];
#pragma unroll
                for (int j2 = 0; j2 < 4; j2++) {
                    bv[j2] = *(const int4*)(stB + dpB0
                                            + (uint32_t)(j2 * 1024) + cB);
                }
#pragma unroll
                for (int j = 0; j < 4; j++) {
                    const int4 a = *(const int4*)(stL + dpA0
                                     + (uint32_t)(j * 512)
                                     + ((j & 1) ? cA1 : cA0));
#pragma unroll
                    for (int j2 = 0; j2 < 4; j2++) {
                        acc_l[j][j2] =
                            dp4a_(a.x, bv[j2].x,
                            dp4a_(a.y, bv[j2].y,
                            dp4a_(a.z, bv[j2].z,
                            dp4a_(a.w, bv[j2].w, acc_l[j][j2]))));
                    }
                }
            }
        }
        __syncthreads();

        if (tid == 0 && i + NSTAGE < NKIT) {
            const int kn = i + NSTAGE;
            const uint32_t st = sbase + s * STAGE;
            MBARRIER_EXPECT_TX(mb0 + 8 * s, STAGE);
            CP_BULK(st,           hiB + ((size_t)kn << 14), APLANE, mb0 + 8 * s);
            CP_BULK(st + OFF_ALO, loB + ((size_t)kn << 14), APLANE, mb0 + 8 * s);
            CP_BULK(st + OFF_B,   bB  + ((size_t)kn << 13), BPLANE, mb0 + 8 * s);
        }
    }

    // ---------------- epilogue ----------------
    __syncthreads();

    int* xch = (int*)sm;                // 128 x XPITCH int32
#pragma unroll
    for (int j = 0; j < 4; j++)
#pragma unroll
        for (int j2 = 0; j2 < 4; j2++) {
            const int r = r0 + lg + 4 * j;
            const int c = c0 + lh + 8 * j2;
            xch[r * XPITCH + c] = acc_l[j][j2];
        }
    __syncthreads();

    {
        const float* rsp = rs + (size_t)e * TT + mb * BM;
        const float* csp = cs + (size_t)e * HH + nb * BN;
        float* Cg = C + ((size_t)e * TT + mb * BM) * HH + nb * BN;

        const int rA = r0 + grp;
        const float sr0 = rsp[rA];
        const float sr1 = rsp[rA + 8];
#pragma unroll
        for (int nt = 0; nt < 4; nt++) {
            const int cn = c0 + nt * 8 + (lane & 3) * 2;
            const float sc0 = csp[cn];
            const float sc1 = csp[cn + 1];
            const int* hh = acc_h[nt];
            const int2 l0 = *(const int2*)(xch + rA * XPITCH + cn);
            const int2 l1 = *(const int2*)(xch + (rA + 8) * XPITCH + cn);
            float2 o0, o1;
            o0.x = fmaf(256.0f, (float)hh[0], (float)l0.x) * (sr0 * sc0);
            o0.y = fmaf(256.0f, (float)hh[1], (float)l0.y) * (sr0 * sc1);
            o1.x = fmaf(256.0f, (float)hh[2], (float)l1.x) * (sr1 * sc0);
            o1.y = fmaf(256.0f, (float)hh[3], (float)l1.y) * (sr1 * sc1);
            *(float2*)(Cg + (size_t)rA * HH + cn)       = o0;
            *(float2*)(Cg + (size_t)(rA + 8) * HH + cn) = o1;
        }
    }
}

// -------------------- launcher --------------------------------------------
extern "C" void kernel_launch(void* const* d_in, const int* in_sizes, int n_in,
                              void* d_out, int out_size) {
    const float* x   = (const float*)d_in[0];
    const int*   w1q = (const int*)d_in[1];
    const float* w1s = (const float*)d_in[2];
    const int*   w2q = (const int*)d_in[3];
    const float* w2s = (const float*)d_in[4];
    float*       out = (float*)d_out;

    void *pw1t, *pw2t, *pahi, *palo, *prs, *ph;
    cudaGetSymbolAddress(&pw1t, g_w1t);
    cudaGetSymbolAddress(&pw2t, g_w2t);
    cudaGetSymbolAddress(&pahi, g_ahi);
    cudaGetSymbolAddress(&palo, g_alo);
    cudaGetSymbolAddress(&prs,  g_rs);
    cudaGetSymbolAddress(&ph,   g_h);

    dim3 cb(32, 8), cg(HH / 32, HH / 32, EE);
    convw_kernel<<<cg, cb>>>(w1q, (int8_t*)pw1t);
    convw_kernel<<<cg, cb>>>(w2q, (int8_t*)pw2t);

    quant_kernel<<<EE * TT, 128>>>(x, (int8_t*)pahi, (int8_t*)palo,
                                   (float*)prs);

    cudaFuncSetAttribute(mix_gemm,
                         cudaFuncAttributeMaxDynamicSharedMemorySize, DYNSMEM);
    dim3 gg(HH / BN, TT / BM, EE);   // (32, 32, 8)

    mix_gemm<<<gg, 512, DYNSMEM>>>((const int8_t*)pahi, (const int8_t*)palo,
                                   (const float*)prs, (const int8_t*)pw1t,
                                   w1s, (float*)ph);

    quant_kernel<<<EE * TT, 128>>>((const float*)ph, (int8_t*)pahi,
                                   (int8_t*)palo, (float*)prs);

    mix_gemm<<<gg, 512, DYNSMEM>>>((const int8_t*)pahi, (const int8_t*)palo,
                                   (const float*)prs, (const int8_t*)pw2t,
                                   w2s, out);
}

// round 11
// speedup vs baseline: 1.0948x; 1.0948x over previous
#include <cuda_runtime.h>
#include <cstdint>

// ---------------------------------------------------------------------------
// out = ((x @ (w1_q*s1)) @ (w2_q*s2)) per expert.  E=8, T=4096, H=2048.
// Exact 16-bit activation split (hi,lo int8 planes).
// R5 compute split (IMMA warps on hi / dp4a warps on lo) at HALF block size
// (256 thr, 128x64 tile, 2-stage bulk-copy ring) so TWO independent CTAs
// share each SM: their pipelines phase-slip and fill each other's sync/LDS
// gaps (R5 showed a +42% window overhead at 1 CTA/SM).
// out = (256*acc_hi + acc_lo) * s_row * wscale_col.
// ---------------------------------------------------------------------------

#define EE 8
#define TT 4096
#define HH 2048

#define BM 128
#define BN 64
#define BK 128
#define NKIT (HH / BK)          // 16
#define APLANE 16384            // 128x128 s8 tile
#define BPLANE 8192             // 64x128 s8 tile
#define STAGE (2 * APLANE + BPLANE)   // 40960
#define OFF_ALO APLANE
#define OFF_B   (2 * APLANE)
#define NSTAGE 2
#define DYNSMEM (NSTAGE * STAGE)      // 81920 -> 2 CTAs/SM
#define XPITCH 68               // padded pitch for lo-acc exchange

// -------------------- scratch (tiled, pre-swizzled) ------------------------
// weights: [e][nb(32)][kb(16)][64x128]   activations: [e][mb(32)][kb(16)][128x128]
__device__ int8_t g_w1t[(size_t)EE * HH * HH];
__device__ int8_t g_w2t[(size_t)EE * HH * HH];
__device__ int8_t g_ahi[(size_t)EE * TT * HH];
__device__ int8_t g_alo[(size_t)EE * TT * HH];
__device__ float  g_rs [(size_t)EE * TT];
__device__ float  g_h  [(size_t)EE * TT * HH];   // layer-1 output fp32

// -------------------- helpers --------------------------------------------
__device__ __forceinline__ uint32_t smem_u32(const void* p) {
    uint32_t a;
    asm("{ .reg .u64 t; cvta.to.shared.u64 t, %1; cvt.u32.u64 %0, t; }"
        : "=r"(a) : "l"(p));
    return a;
}

#define MBARRIER_INIT(mbar, cnt) \
    asm volatile("mbarrier.init.shared.b64 [%0], %1;" \
                 :: "r"((uint32_t)(mbar)), "r"((uint32_t)(cnt)) : "memory")
#define MBARRIER_EXPECT_TX(mbar, tx) \
    asm volatile("mbarrier.arrive.expect_tx.shared.b64 _, [%0], %1;" \
                 :: "r"((uint32_t)(mbar)), "r"((uint32_t)(tx)) : "memory")

#define MBARRIER_WAIT_PARITY(mbar, par) do {                                   \
    uint32_t _m = (uint32_t)(mbar);                                            \
    uint32_t _p = (uint32_t)(par);                                             \
    uint32_t _done;                                                            \
    asm volatile("{\n\t.reg .pred p;\n\t"                                      \
        "mbarrier.try_wait.parity.shared.b64 p, [%1], %2;\n\t"                 \
        "selp.b32 %0, 1, 0, p;\n\t}"                                           \
        : "=r"(_done) : "r"(_m), "r"(_p) : "memory");                          \
    if (!_done) {                                                              \
        asm volatile("{\n\t.reg .pred P1;\n\t"                                 \
            "WL_%=:\n\t"                                                       \
            "mbarrier.try_wait.parity.shared.b64 P1, [%0], %1;\n\t"            \
            "@P1 bra.uni WD_%=;\n\t"                                           \
            "bra.uni WL_%=;\n\t"                                               \
            "WD_%=:\n\t}"                                                      \
            :: "r"(_m), "r"(_p) : "memory");                                   \
    }                                                                          \
} while (0)

#define CP_BULK(dst, src, nbytes, mbar) \
    asm volatile( \
        "cp.async.bulk.shared::cluster.global.mbarrier::complete_tx::bytes " \
        "[%0], [%1], %2, [%3];" \
        :: "r"((uint32_t)(dst)), "l"(src), "r"((uint32_t)(nbytes)), \
           "r"((uint32_t)(mbar)) : "memory")

__device__ __forceinline__ void imma(int* d, const uint32_t* a,
                                     const uint32_t* b) {
    asm volatile(
        "mma.sync.aligned.m16n8k32.row.col.s32.s8.s8.s32 "
        "{%0,%1,%2,%3},{%4,%5,%6,%7},{%8,%9},{%0,%1,%2,%3};"
        : "+r"(d[0]), "+r"(d[1]), "+r"(d[2]), "+r"(d[3])
        : "r"(a[0]), "r"(a[1]), "r"(a[2]), "r"(a[3]),
          "r"(b[0]), "r"(b[1]));
}

__device__ __forceinline__ int dp4a_(int a, int b, int c) {
    int d;
    asm("dp4a.s32.s32 %0, %1, %2, %3;" : "=r"(d) : "r"(a), "r"(b), "r"(c));
    return d;
}

// -------------------- weight convert + transpose + tile + swizzle ----------
// W int32 [E][k][n] -> tiles [e][nb(32)][kb(16)][64x128] int8, chunk-swizzled
__global__ void convw_kernel(const int* __restrict__ W,
                             int8_t* __restrict__ O) {
    __shared__ int8_t tile[32][33];
    const int e  = blockIdx.z;
    const int n0 = blockIdx.x * 32;
    const int k0 = blockIdx.y * 32;
    const int tx = threadIdx.x, ty = threadIdx.y;

    const int* src = W + ((size_t)e * HH + k0) * HH + n0;
#pragma unroll
    for (int r = 0; r < 4; r++) {
        tile[ty + r * 8][tx] = (int8_t)src[(size_t)(ty + r * 8) * HH + tx];
    }
    __syncthreads();
    const int t  = ty * 32 + tx;
    const int nr = t >> 3;              // 0..31
    const int c4 = (t & 7) * 4;         // 0..28
    uint32_t p = (uint32_t)(uint8_t)tile[c4 + 0][nr]
               | ((uint32_t)(uint8_t)tile[c4 + 1][nr] << 8)
               | ((uint32_t)(uint8_t)tile[c4 + 2][nr] << 16)
               | ((uint32_t)(uint8_t)tile[c4 + 3][nr] << 24);
    const int ng = n0 + nr;
    const int nb = ng >> 6, rowT = ng & 63;
    const int kin = (k0 & 127) + c4;
    const int ch  = kin >> 4;
    const uint32_t sw = (uint32_t)(((ch ^ (rowT & 7)) & 7) << 4) + (kin & 15);
    int8_t* dst = O + (((size_t)(e * 32 + nb) * 16 + (k0 >> 7)) << 13)
                    + rowT * 128 + sw;
    *(uint32_t*)dst = p;
}

// -------------------- activation quantize (tiled + swizzled output) --------
__global__ void quant_kernel(const float* __restrict__ X,
                             int8_t* __restrict__ Qh,
                             int8_t* __restrict__ Ql,
                             float* __restrict__ RS) {
    const int row = blockIdx.x;          // 0 .. EE*TT-1
    const float* x = X + (size_t)row * HH;
    const int t = threadIdx.x;           // 0..127

    float4 v[4];
#pragma unroll
    for (int j = 0; j < 4; j++) v[j] = ((const float4*)x)[t * 4 + j];

    float m = 0.0f;
#pragma unroll
    for (int j = 0; j < 4; j++) {
        m = fmaxf(m, fabsf(v[j].x)); m = fmaxf(m, fabsf(v[j].y));
        m = fmaxf(m, fabsf(v[j].z)); m = fmaxf(m, fabsf(v[j].w));
    }
#pragma unroll
    for (int o = 16; o; o >>= 1)
        m = fmaxf(m, __shfl_xor_sync(0xFFFFFFFFu, m, o));
    __shared__ float wr[4];
    if ((t & 31) == 0) wr[t >> 5] = m;
    __syncthreads();
    float mx = fmaxf(fmaxf(wr[0], wr[1]), fmaxf(wr[2], wr[3]));
    mx = fmaxf(mx, 1e-20f);
    const float inv = 32600.0f / mx;

    uint32_t hw[4], lw[4];
#pragma unroll
    for (int j = 0; j < 4; j++) {
        const int q0 = __float2int_rn(v[j].x * inv);
        const int q1 = __float2int_rn(v[j].y * inv);
        const int q2 = __float2int_rn(v[j].z * inv);
        const int q3 = __float2int_rn(v[j].w * inv);
        const int h0 = (q0 + 128) >> 8, h1 = (q1 + 128) >> 8;
        const int h2 = (q2 + 128) >> 8, h3 = (q3 + 128) >> 8;
        const int l0 = q0 - (h0 << 8), l1 = q1 - (h1 << 8);
        const int l2 = q2 - (h2 << 8), l3 = q3 - (h3 << 8);
        hw[j] = (h0 & 255) | ((h1 & 255) << 8) | ((h2 & 255) << 16)
              | ((uint32_t)(h3 & 255) << 24);
        lw[j] = (l0 & 255) | ((l1 & 255) << 8) | ((l2 & 255) << 16)
              | ((uint32_t)(l3 & 255) << 24);
    }

    const int e  = row >> 12;
    const int mm = row & 4095;
    const int kb = t >> 3;               // 0..15
    const int ch = t & 7;
    const int rowT = mm & 127;
    const uint32_t sw = (uint32_t)(((ch ^ (rowT & 7)) & 7) << 4);
    const size_t base = (((size_t)(e * 32 + (mm >> 7)) * 16 + kb) << 14)
                      + rowT * 128 + sw;
    *(int4*)(Qh + base) = make_int4(hw[0], hw[1], hw[2], hw[3]);
    *(int4*)(Ql + base) = make_int4(lw[0], lw[1], lw[2], lw[3]);
    if (t == 0) RS[row] = mx / 32600.0f;
}

// -------------------- 256-thread warp-specialized GEMM ---------------------
// warps 0-3: hi plane IMMA (64x32 tiles); warps 4-7: lo plane DP4A (32x64)
__global__ void __launch_bounds__(256, 2)
imma_gemm(const int8_t* __restrict__ Ah, const int8_t* __restrict__ Al,
          const float* __restrict__ rs, const int8_t* __restrict__ Bt,
          const float* __restrict__ cs, float* __restrict__ C) {
    extern __shared__ __align__(128) char sm[];
    __shared__ __align__(8) uint64_t mbar_s[NSTAGE];
    const uint32_t sbase = smem_u32(sm);
    const uint32_t mb0 = smem_u32(mbar_s);
    const int tid = threadIdx.x;
    const int lane = tid & 31, wid = tid >> 5;

    const int e  = blockIdx.z;
    const int mb = blockIdx.y;           // 0..31
    const int nb = blockIdx.x;           // 0..31

    const int8_t* hiB = Ah + (((size_t)(e * 32 + mb) * 16) << 14);
    const int8_t* loB = Al + (((size_t)(e * 32 + mb) * 16) << 14);
    const int8_t* bB  = Bt + (((size_t)(e * 32 + nb) * 16) << 13);

    // ---- mma-warp config (wid 0..3): hi plane, 64x32 tiles ----
    const int grp = lane >> 2;
    const int tg4 = (lane & 3) * 4;
    const int wm = wid >> 1;             // 0..1
    const int wn = wid & 1;              // 0..1
    uint32_t baseA[8], baseB[4];
#pragma unroll
    for (int j = 0; j < 8; j++)
        baseA[j] = (uint32_t)((wm * 64 + j * 8 + grp) * 128 + tg4);
#pragma unroll
    for (int j = 0; j < 4; j++)
        baseB[j] = (uint32_t)((wn * 32 + j * 8 + grp) * 128 + tg4);

    // ---- dp4a-warp config (wid 4..7): lo plane, 32x64 tiles ----
    const int wtr = wid - 4;             // 0..3 -> rows wtr*32
    const int lg = lane & 3;
    const int lh = lane >> 2;
    const uint32_t dpA0 = (uint32_t)((wtr * 32 + lg) * 128);
    const uint32_t dpB0 = (uint32_t)(lh * 128);

    int acc_h[4][4][4];
    int acc_lo[8][8];
    if (wid < 4) {
#pragma unroll
        for (int a = 0; a < 4; a++)
#pragma unroll
            for (int b = 0; b < 4; b++)
#pragma unroll
                for (int c = 0; c < 4; c++) acc_h[a][b][c] = 0;
    } else {
#pragma unroll
        for (int a = 0; a < 8; a++)
#pragma unroll
            for (int b = 0; b < 8; b++) acc_lo[a][b] = 0;
    }

    if (tid == 0) {
#pragma unroll
        for (int s = 0; s < NSTAGE; s++) MBARRIER_INIT(mb0 + 8 * s, 1);
    }
    __syncthreads();

    if (tid == 0) {
#pragma unroll
        for (int p = 0; p < NSTAGE; p++) {
            const uint32_t st = sbase + p * STAGE;
            MBARRIER_EXPECT_TX(mb0 + 8 * p, STAGE);
            CP_BULK(st,           hiB + ((size_t)p << 14), APLANE, mb0 + 8 * p);
            CP_BULK(st + OFF_ALO, loB + ((size_t)p << 14), APLANE, mb0 + 8 * p);
            CP_BULK(st + OFF_B,   bB  + ((size_t)p << 13), BPLANE, mb0 + 8 * p);
        }
    }

#pragma unroll 1
    for (int i = 0; i < NKIT; i++) {
        const int s = i & 1;
        MBARRIER_WAIT_PARITY(mb0 + 8 * s, (i >> 1) & 1);

        const char* stA = sm + s * STAGE;
        const char* stL = stA + OFF_ALO;
        const char* stB = stA + OFF_B;

        if (wid < 4) {
            // ================= tensor pipe: hi plane =================
#pragma unroll
            for (int ks = 0; ks < 4; ks++) {
                const uint32_t xa = (uint32_t)((((2 * ks) ^ grp) & 7) << 4);
                const uint32_t xb = (uint32_t)((((2 * ks + 1) ^ grp) & 7) << 4);

                uint32_t bf[4][2];
#pragma unroll
                for (int nt = 0; nt < 4; nt++) {
                    bf[nt][0] = *(const uint32_t*)(stB + baseB[nt] + xa);
                    bf[nt][1] = *(const uint32_t*)(stB + baseB[nt] + xb);
                }
#pragma unroll
                for (int mt = 0; mt < 4; mt++) {
                    uint32_t ah[4];
                    ah[0] = *(const uint32_t*)(stA + baseA[2 * mt]     + xa);
                    ah[1] = *(const uint32_t*)(stA + baseA[2 * mt + 1] + xa);
                    ah[2] = *(const uint32_t*)(stA + baseA[2 * mt]     + xb);
                    ah[3] = *(const uint32_t*)(stA + baseA[2 * mt + 1] + xb);
#pragma unroll
                    for (int nt = 0; nt < 4; nt++) {
                        imma(acc_h[mt][nt], ah, bf[nt]);
                    }
                }
            }
        } else {
            // ================= integer pipe: lo plane =================
#pragma unroll 2
            for (int kb = 0; kb < BK; kb += 16) {
                const uint32_t cA0 =
                    (uint32_t)(((((kb >> 4)) ^ lg) & 7) << 4);
                const uint32_t cA1 = cA0 ^ 64u;
                const uint32_t cB =
                    (uint32_t)(((((kb >> 4)) ^ lh) & 7) << 4);
                int4 bv[8];
#pragma unroll
                for (int j2 = 0; j2 < 8; j2++) {
                    bv[j2] = *(const int4*)(stB + dpB0
                                            + (uint32_t)(j2 * 1024) + cB);
                }
#pragma unroll
                for (int j = 0; j < 8; j++) {
                    const int4 a = *(const int4*)(stL + dpA0
                                     + (uint32_t)(j * 512)
                                     + ((j & 1) ? cA1 : cA0));
#pragma unroll
                    for (int j2 = 0; j2 < 8; j2++) {
                        acc_lo[j][j2] =
                            dp4a_(a.x, bv[j2].x,
                            dp4a_(a.y, bv[j2].y,
                            dp4a_(a.z, bv[j2].z,
                            dp4a_(a.w, bv[j2].w, acc_lo[j][j2]))));
                    }
                }
            }
        }
        __syncthreads();

        if (tid == 0 && i + NSTAGE < NKIT) {
            const int kn = i + NSTAGE;
            const uint32_t st = sbase + s * STAGE;
            MBARRIER_EXPECT_TX(mb0 + 8 * s, STAGE);
            CP_BULK(st,           hiB + ((size_t)kn << 14), APLANE, mb0 + 8 * s);
            CP_BULK(st + OFF_ALO, loB + ((size_t)kn << 14), APLANE, mb0 + 8 * s);
            CP_BULK(st + OFF_B,   bB  + ((size_t)kn << 13), BPLANE, mb0 + 8 * s);
        }
    }

    // ---------------- epilogue ----------------
    __syncthreads();

    int* xch = (int*)sm;                // 128 x XPITCH int32 (34.8KB)
    if (wid >= 4) {
#pragma unroll
        for (int j = 0; j < 8; j++)
#pragma unroll
            for (int j2 = 0; j2 < 8; j2++) {
                const int r = wtr * 32 + lg + 4 * j;
                const int c = lh + 8 * j2;
                xch[r * XPITCH + c] = acc_lo[j][j2];
            }
    }
    __syncthreads();

    if (wid < 4) {
        const float* rsp = rs + (size_t)e * TT + mb * BM;
        const float* csp = cs + (size_t)e * HH + nb * BN;
        float* Cg = C + ((size_t)e * TT + mb * BM) * HH + nb * BN;

#pragma unroll
        for (int mt = 0; mt < 4; mt++) {
            const int rA = wm * 64 + mt * 16 + grp;
            const float sr0 = rsp[rA];
            const float sr1 = rsp[rA + 8];
#pragma unroll
            for (int nt = 0; nt < 4; nt++) {
                const int cn = wn * 32 + nt * 8 + (lane & 3) * 2;
                const float sc0 = csp[cn];
                const float sc1 = csp[cn + 1];
                const int* hh = acc_h[mt][nt];
                const int2 l0 = *(const int2*)(xch + rA * XPITCH + cn);
                const int2 l1 = *(const int2*)(xch + (rA + 8) * XPITCH + cn);
                float2 r0, r1;
                r0.x = fmaf(256.0f, (float)hh[0], (float)l0.x) * (sr0 * sc0);
                r0.y = fmaf(256.0f, (float)hh[1], (float)l0.y) * (sr0 * sc1);
                r1.x = fmaf(256.0f, (float)hh[2], (float)l1.x) * (sr1 * sc0);
                r1.y = fmaf(256.0f, (float)hh[3], (float)l1.y) * (sr1 * sc1);
                *(float2*)(Cg + (size_t)rA * HH + cn)       = r0;
                *(float2*)(Cg + (size_t)(rA + 8) * HH + cn) = r1;
            }
        }
    }
}

// -------------------- launcher --------------------------------------------
extern "C" void kernel_launch(void* const* d_in, const int* in_sizes, int n_in,
                              void* d_out, int out_size) {
    const float* x   = (const float*)d_in[0];
    const int*   w1q = (const int*)d_in[1];
    const float* w1s = (const float*)d_in[2];
    const int*   w2q = (const int*)d_in[3];
    const float* w2s = (const float*)d_in[4];
    float*       out = (float*)d_out;

    void *pw1t, *pw2t, *pahi, *palo, *prs, *ph;
    cudaGetSymbolAddress(&pw1t, g_w1t);
    cudaGetSymbolAddress(&pw2t, g_w2t);
    cudaGetSymbolAddress(&pahi, g_ahi);
    cudaGetSymbolAddress(&palo, g_alo);
    cudaGetSymbolAddress(&prs,  g_rs);
    cudaGetSymbolAddress(&ph,   g_h);

    dim3 cb(32, 8), cg(HH / 32, HH / 32, EE);
    convw_kernel<<<cg, cb>>>(w1q, (int8_t*)pw1t);
    convw_kernel<<<cg, cb>>>(w2q, (int8_t*)pw2t);

    quant_kernel<<<EE * TT, 128>>>(x, (int8_t*)pahi, (int8_t*)palo,
                                   (float*)prs);

    cudaFuncSetAttribute(imma_gemm,
                         cudaFuncAttributeMaxDynamicSharedMemorySize, DYNSMEM);
    dim3 gg(HH / BN, TT / BM, EE);   // (32, 32, 8)

    imma_gemm<<<gg, 256, DYNSMEM>>>((const int8_t*)pahi, (const int8_t*)palo,
                                    (const float*)prs, (const int8_t*)pw1t,
                                    w1s, (float*)ph);

    quant_kernel<<<EE * TT, 128>>>((const float*)ph, (int8_t*)pahi,
                                   (int8_t*)palo, (float*)prs);

    imma_gemm<<<gg, 256, DYNSMEM>>>((const int8_t*)pahi, (const int8_t*)palo,
                                    (const float*)prs, (const int8_t*)pw2t,
                                    w2s, out);
}

// round 12
// speedup vs baseline: 1.1152x; 1.0186x over previous
#include <cuda_runtime.h>
#include <cstdint>

// ---------------------------------------------------------------------------
// out = ((x @ (w1_q*s1)) @ (w2_q*s2)) per expert.  E=8, T=4096, H=2048.
// Exact 16-bit activation split (hi,lo int8 planes).
// R11 (2 CTAs/SM, IMMA-hi / DP4A-lo warp split, bulk-copy ring) +
// PRODUCER/CONSUMER DECOUPLING: per-stage free[] mbarriers replace the
// per-k-iter __syncthreads, so the IMMA and dp4a warp groups never join —
// each runs at its own rate with up to one stage of slack.
// out = (256*acc_hi + acc_lo) * s_row * wscale_col.
// ---------------------------------------------------------------------------

#define EE 8
#define TT 4096
#define HH 2048

#define BM 128
#define BN 64
#define BK 128
#define NKIT (HH / BK)          // 16
#define APLANE 16384            // 128x128 s8 tile
#define BPLANE 8192             // 64x128 s8 tile
#define STAGE (2 * APLANE + BPLANE)   // 40960
#define OFF_ALO APLANE
#define OFF_B   (2 * APLANE)
#define NSTAGE 2
#define DYNSMEM (NSTAGE * STAGE)      // 81920 -> 2 CTAs/SM
#define XPITCH 68               // padded pitch for lo-acc exchange

// -------------------- scratch (tiled, pre-swizzled) ------------------------
// weights: [e][nb(32)][kb(16)][64x128]   activations: [e][mb(32)][kb(16)][128x128]
__device__ int8_t g_w1t[(size_t)EE * HH * HH];
__device__ int8_t g_w2t[(size_t)EE * HH * HH];
__device__ int8_t g_ahi[(size_t)EE * TT * HH];
__device__ int8_t g_alo[(size_t)EE * TT * HH];
__device__ float  g_rs [(size_t)EE * TT];
__device__ float  g_h  [(size_t)EE * TT * HH];   // layer-1 output fp32

// -------------------- helpers --------------------------------------------
__device__ __forceinline__ uint32_t smem_u32(const void* p) {
    uint32_t a;
    asm("{ .reg .u64 t; cvta.to.shared.u64 t, %1; cvt.u32.u64 %0, t; }"
        : "=r"(a) : "l"(p));
    return a;
}

#define MBARRIER_INIT(mbar, cnt) \
    asm volatile("mbarrier.init.shared.b64 [%0], %1;" \
                 :: "r"((uint32_t)(mbar)), "r"((uint32_t)(cnt)) : "memory")
#define MBARRIER_EXPECT_TX(mbar, tx) \
    asm volatile("mbarrier.arrive.expect_tx.shared.b64 _, [%0], %1;" \
                 :: "r"((uint32_t)(mbar)), "r"((uint32_t)(tx)) : "memory")
#define MBARRIER_ARRIVE(mbar) \
    asm volatile("mbarrier.arrive.shared.b64 _, [%0];" \
                 :: "r"((uint32_t)(mbar)) : "memory")

#define MBARRIER_WAIT_PARITY(mbar, par) do {                                   \
    uint32_t _m = (uint32_t)(mbar);                                            \
    uint32_t _p = (uint32_t)(par);                                             \
    uint32_t _done;                                                            \
    asm volatile("{\n\t.reg .pred p;\n\t"                                      \
        "mbarrier.try_wait.parity.shared.b64 p, [%1], %2;\n\t"                 \
        "selp.b32 %0, 1, 0, p;\n\t}"                                           \
        : "=r"(_done) : "r"(_m), "r"(_p) : "memory");                          \
    if (!_done) {                                                              \
        asm volatile("{\n\t.reg .pred P1;\n\t"                                 \
            "WL_%=:\n\t"                                                       \
            "mbarrier.try_wait.parity.shared.b64 P1, [%0], %1;\n\t"            \
            "@P1 bra.uni WD_%=;\n\t"                                           \
            "bra.uni WL_%=;\n\t"                                               \
            "WD_%=:\n\t}"                                                      \
            :: "r"(_m), "r"(_p) : "memory");                                   \
    }                                                                          \
} while (0)

#define CP_BULK(dst, src, nbytes, mbar) \
    asm volatile( \
        "cp.async.bulk.shared::cluster.global.mbarrier::complete_tx::bytes " \
        "[%0], [%1], %2, [%3];" \
        :: "r"((uint32_t)(dst)), "l"(src), "r"((uint32_t)(nbytes)), \
           "r"((uint32_t)(mbar)) : "memory")

__device__ __forceinline__ void imma(int* d, const uint32_t* a,
                                     const uint32_t* b) {
    asm volatile(
        "mma.sync.aligned.m16n8k32.row.col.s32.s8.s8.s32 "
        "{%0,%1,%2,%3},{%4,%5,%6,%7},{%8,%9},{%0,%1,%2,%3};"
        : "+r"(d[0]), "+r"(d[1]), "+r"(d[2]), "+r"(d[3])
        : "r"(a[0]), "r"(a[1]), "r"(a[2]), "r"(a[3]),
          "r"(b[0]), "r"(b[1]));
}

__device__ __forceinline__ int dp4a_(int a, int b, int c) {
    int d;
    asm("dp4a.s32.s32 %0, %1, %2, %3;" : "=r"(d) : "r"(a), "r"(b), "r"(c));
    return d;
}

// -------------------- weight convert + transpose + tile + swizzle ----------
// W int32 [E][k][n] -> tiles [e][nb(32)][kb(16)][64x128] int8, chunk-swizzled
__global__ void convw_kernel(const int* __restrict__ W,
                             int8_t* __restrict__ O) {
    __shared__ int8_t tile[32][33];
    const int e  = blockIdx.z;
    const int n0 = blockIdx.x * 32;
    const int k0 = blockIdx.y * 32;
    const int tx = threadIdx.x, ty = threadIdx.y;

    const int* src = W + ((size_t)e * HH + k0) * HH + n0;
#pragma unroll
    for (int r = 0; r < 4; r++) {
        tile[ty + r * 8][tx] = (int8_t)src[(size_t)(ty + r * 8) * HH + tx];
    }
    __syncthreads();
    const int t  = ty * 32 + tx;
    const int nr = t >> 3;              // 0..31
    const int c4 = (t & 7) * 4;         // 0..28
    uint32_t p = (uint32_t)(uint8_t)tile[c4 + 0][nr]
               | ((uint32_t)(uint8_t)tile[c4 + 1][nr] << 8)
               | ((uint32_t)(uint8_t)tile[c4 + 2][nr] << 16)
               | ((uint32_t)(uint8_t)tile[c4 + 3][nr] << 24);
    const int ng = n0 + nr;
    const int nb = ng >> 6, rowT = ng & 63;
    const int kin = (k0 & 127) + c4;
    const int ch  = kin >> 4;
    const uint32_t sw = (uint32_t)(((ch ^ (rowT & 7)) & 7) << 4) + (kin & 15);
    int8_t* dst = O + (((size_t)(e * 32 + nb) * 16 + (k0 >> 7)) << 13)
                    + rowT * 128 + sw;
    *(uint32_t*)dst = p;
}

// -------------------- activation quantize (tiled + swizzled output) --------
__global__ void quant_kernel(const float* __restrict__ X,
                             int8_t* __restrict__ Qh,
                             int8_t* __restrict__ Ql,
                             float* __restrict__ RS) {
    const int row = blockIdx.x;          // 0 .. EE*TT-1
    const float* x = X + (size_t)row * HH;
    const int t = threadIdx.x;           // 0..127

    float4 v[4];
#pragma unroll
    for (int j = 0; j < 4; j++) v[j] = ((const float4*)x)[t * 4 + j];

    float m = 0.0f;
#pragma unroll
    for (int j = 0; j < 4; j++) {
        m = fmaxf(m, fabsf(v[j].x)); m = fmaxf(m, fabsf(v[j].y));
        m = fmaxf(m, fabsf(v[j].z)); m = fmaxf(m, fabsf(v[j].w));
    }
#pragma unroll
    for (int o = 16; o; o >>= 1)
        m = fmaxf(m, __shfl_xor_sync(0xFFFFFFFFu, m, o));
    __shared__ float wr[4];
    if ((t & 31) == 0) wr[t >> 5] = m;
    __syncthreads();
    float mx = fmaxf(fmaxf(wr[0], wr[1]), fmaxf(wr[2], wr[3]));
    mx = fmaxf(mx, 1e-20f);
    const float inv = 32600.0f / mx;

    uint32_t hw[4], lw[4];
#pragma unroll
    for (int j = 0; j < 4; j++) {
        const int q0 = __float2int_rn(v[j].x * inv);
        const int q1 = __float2int_rn(v[j].y * inv);
        const int q2 = __float2int_rn(v[j].z * inv);
        const int q3 = __float2int_rn(v[j].w * inv);
        const int h0 = (q0 + 128) >> 8, h1 = (q1 + 128) >> 8;
        const int h2 = (q2 + 128) >> 8, h3 = (q3 + 128) >> 8;
        const int l0 = q0 - (h0 << 8), l1 = q1 - (h1 << 8);
        const int l2 = q2 - (h2 << 8), l3 = q3 - (h3 << 8);
        hw[j] = (h0 & 255) | ((h1 & 255) << 8) | ((h2 & 255) << 16)
              | ((uint32_t)(h3 & 255) << 24);
        lw[j] = (l0 & 255) | ((l1 & 255) << 8) | ((l2 & 255) << 16)
              | ((uint32_t)(l3 & 255) << 24);
    }

    const int e  = row >> 12;
    const int mm = row & 4095;
    const int kb = t >> 3;               // 0..15
    const int ch = t & 7;
    const int rowT = mm & 127;
    const uint32_t sw = (uint32_t)(((ch ^ (rowT & 7)) & 7) << 4);
    const size_t base = (((size_t)(e * 32 + (mm >> 7)) * 16 + kb) << 14)
                      + rowT * 128 + sw;
    *(int4*)(Qh + base) = make_int4(hw[0], hw[1], hw[2], hw[3]);
    *(int4*)(Ql + base) = make_int4(lw[0], lw[1], lw[2], lw[3]);
    if (t == 0) RS[row] = mx / 32600.0f;
}

// -------------------- decoupled warp-specialized GEMM ----------------------
// warps 0-3: hi plane IMMA (64x32 tiles); warps 4-7: lo plane DP4A (32x64)
// full[s] mbarriers: bulk-copy completion; free[s]: 256-thread consume marks.
__global__ void __launch_bounds__(256, 2)
imma_gemm(const int8_t* __restrict__ Ah, const int8_t* __restrict__ Al,
          const float* __restrict__ rs, const int8_t* __restrict__ Bt,
          const float* __restrict__ cs, float* __restrict__ C) {
    extern __shared__ __align__(128) char sm[];
    __shared__ __align__(8) uint64_t mbar_s[2 * NSTAGE];  // full0,full1,free0,free1
    const uint32_t sbase = smem_u32(sm);
    const uint32_t mbF = smem_u32(mbar_s);          // full
    const uint32_t mbE = mbF + 8 * NSTAGE;          // free
    const int tid = threadIdx.x;
    const int lane = tid & 31, wid = tid >> 5;

    const int e  = blockIdx.z;
    const int mb = blockIdx.y;           // 0..31
    const int nb = blockIdx.x;           // 0..31

    const int8_t* hiB = Ah + (((size_t)(e * 32 + mb) * 16) << 14);
    const int8_t* loB = Al + (((size_t)(e * 32 + mb) * 16) << 14);
    const int8_t* bB  = Bt + (((size_t)(e * 32 + nb) * 16) << 13);

    // ---- mma-warp config (wid 0..3): hi plane, 64x32 tiles ----
    const int grp = lane >> 2;
    const int tg4 = (lane & 3) * 4;
    const int wm = wid >> 1;             // 0..1
    const int wn = wid & 1;              // 0..1
    uint32_t baseA[8], baseB[4];
#pragma unroll
    for (int j = 0; j < 8; j++)
        baseA[j] = (uint32_t)((wm * 64 + j * 8 + grp) * 128 + tg4);
#pragma unroll
    for (int j = 0; j < 4; j++)
        baseB[j] = (uint32_t)((wn * 32 + j * 8 + grp) * 128 + tg4);

    // ---- dp4a-warp config (wid 4..7): lo plane, 32x64 tiles ----
    const int wtr = wid - 4;             // 0..3 -> rows wtr*32
    const int lg = lane & 3;
    const int lh = lane >> 2;
    const uint32_t dpA0 = (uint32_t)((wtr * 32 + lg) * 128);
    const uint32_t dpB0 = (uint32_t)(lh * 128);

    int acc_h[4][4][4];
    int acc_lo[8][8];
    if (wid < 4) {
#pragma unroll
        for (int a = 0; a < 4; a++)
#pragma unroll
            for (int b = 0; b < 4; b++)
#pragma unroll
                for (int c = 0; c < 4; c++) acc_h[a][b][c] = 0;
    } else {
#pragma unroll
        for (int a = 0; a < 8; a++)
#pragma unroll
            for (int b = 0; b < 8; b++) acc_lo[a][b] = 0;
    }

    if (tid == 0) {
#pragma unroll
        for (int s = 0; s < NSTAGE; s++) {
            MBARRIER_INIT(mbF + 8 * s, 1);     // loader expect_tx
            MBARRIER_INIT(mbE + 8 * s, 256);   // all consumers
        }
    }
    __syncthreads();

    if (tid == 0) {
#pragma unroll
        for (int p = 0; p < NSTAGE; p++) {
            const uint32_t st = sbase + p * STAGE;
            MBARRIER_EXPECT_TX(mbF + 8 * p, STAGE);
            CP_BULK(st,           hiB + ((size_t)p << 14), APLANE, mbF + 8 * p);
            CP_BULK(st + OFF_ALO, loB + ((size_t)p << 14), APLANE, mbF + 8 * p);
            CP_BULK(st + OFF_B,   bB  + ((size_t)p << 13), BPLANE, mbF + 8 * p);
        }
    }

#pragma unroll 1
    for (int i = 0; i < NKIT; i++) {
        const int s = i & 1;
        const int ph = (i >> 1) & 1;
        MBARRIER_WAIT_PARITY(mbF + 8 * s, ph);

        const char* stA = sm + s * STAGE;
        const char* stL = stA + OFF_ALO;
        const char* stB = stA + OFF_B;

        if (wid < 4) {
            // ================= tensor pipe: hi plane =================
#pragma unroll
            for (int ks = 0; ks < 4; ks++) {
                const uint32_t xa = (uint32_t)((((2 * ks) ^ grp) & 7) << 4);
                const uint32_t xb = (uint32_t)((((2 * ks + 1) ^ grp) & 7) << 4);

                uint32_t bf[4][2];
#pragma unroll
                for (int nt = 0; nt < 4; nt++) {
                    bf[nt][0] = *(const uint32_t*)(stB + baseB[nt] + xa);
                    bf[nt][1] = *(const uint32_t*)(stB + baseB[nt] + xb);
                }
#pragma unroll
                for (int mt = 0; mt < 4; mt++) {
                    uint32_t ah[4];
                    ah[0] = *(const uint32_t*)(stA + baseA[2 * mt]     + xa);
                    ah[1] = *(const uint32_t*)(stA + baseA[2 * mt + 1] + xa);
                    ah[2] = *(const uint32_t*)(stA + baseA[2 * mt]     + xb);
                    ah[3] = *(const uint32_t*)(stA + baseA[2 * mt + 1] + xb);
#pragma unroll
                    for (int nt = 0; nt < 4; nt++) {
                        imma(acc_h[mt][nt], ah, bf[nt]);
                    }
                }
            }
        } else {
            // ================= integer pipe: lo plane =================
#pragma unroll 2
            for (int kb = 0; kb < BK; kb += 16) {
                const uint32_t cA0 =
                    (uint32_t)(((((kb >> 4)) ^ lg) & 7) << 4);
                const uint32_t cA1 = cA0 ^ 64u;
                const uint32_t cB =
                    (uint32_t)(((((kb >> 4)) ^ lh) & 7) << 4);
                int4 bv[8];
#pragma unroll
                for (int j2 = 0; j2 < 8; j2++) {
                    bv[j2] = *(const int4*)(stB + dpB0
                                            + (uint32_t)(j2 * 1024) + cB);
                }
#pragma unroll
                for (int j = 0; j < 8; j++) {
                    const int4 a = *(const int4*)(stL + dpA0
                                     + (uint32_t)(j * 512)
                                     + ((j & 1) ? cA1 : cA0));
#pragma unroll
                    for (int j2 = 0; j2 < 8; j2++) {
                        acc_lo[j][j2] =
                            dp4a_(a.x, bv[j2].x,
                            dp4a_(a.y, bv[j2].y,
                            dp4a_(a.z, bv[j2].z,
                            dp4a_(a.w, bv[j2].w, acc_lo[j][j2]))));
                    }
                }
            }
        }

        // mark stage consumed (non-blocking for everyone)
        MBARRIER_ARRIVE(mbE + 8 * s);

        // refiller: wait until all 256 consumed, then re-issue bulk copies
        if (tid == 0 && i + NSTAGE < NKIT) {
            MBARRIER_WAIT_PARITY(mbE + 8 * s, ph);
            const int kn = i + NSTAGE;
            const uint32_t st = sbase + s * STAGE;
            MBARRIER_EXPECT_TX(mbF + 8 * s, STAGE);
            CP_BULK(st,           hiB + ((size_t)kn << 14), APLANE, mbF + 8 * s);
            CP_BULK(st + OFF_ALO, loB + ((size_t)kn << 14), APLANE, mbF + 8 * s);
            CP_BULK(st + OFF_B,   bB  + ((size_t)kn << 13), BPLANE, mbF + 8 * s);
        }
    }

    // ---------------- epilogue ----------------
    __syncthreads();

    int* xch = (int*)sm;                // 128 x XPITCH int32 (34.8KB)
    if (wid >= 4) {
#pragma unroll
        for (int j = 0; j < 8; j++)
#pragma unroll
            for (int j2 = 0; j2 < 8; j2++) {
                const int r = wtr * 32 + lg + 4 * j;
                const int c = lh + 8 * j2;
                xch[r * XPITCH + c] = acc_lo[j][j2];
            }
    }
    __syncthreads();

    if (wid < 4) {
        const float* rsp = rs + (size_t)e * TT + mb * BM;
        const float* csp = cs + (size_t)e * HH + nb * BN;
        float* Cg = C + ((size_t)e * TT + mb * BM) * HH + nb * BN;

#pragma unroll
        for (int mt = 0; mt < 4; mt++) {
            const int rA = wm * 64 + mt * 16 + grp;
            const float sr0 = rsp[rA];
            const float sr1 = rsp[rA + 8];
#pragma unroll
            for (int nt = 0; nt < 4; nt++) {
                const int cn = wn * 32 + nt * 8 + (lane & 3) * 2;
                const float sc0 = csp[cn];
                const float sc1 = csp[cn + 1];
                const int* hh = acc_h[mt][nt];
                const int2 l0 = *(const int2*)(xch + rA * XPITCH + cn);
                const int2 l1 = *(const int2*)(xch + (rA + 8) * XPITCH + cn);
                float2 r0, r1;
                r0.x = fmaf(256.0f, (float)hh[0], (float)l0.x) * (sr0 * sc0);
                r0.y = fmaf(256.0f, (float)hh[1], (float)l0.y) * (sr0 * sc1);
                r1.x = fmaf(256.0f, (float)hh[2], (float)l1.x) * (sr1 * sc0);
                r1.y = fmaf(256.0f, (float)hh[3], (float)l1.y) * (sr1 * sc1);
                *(float2*)(Cg + (size_t)rA * HH + cn)       = r0;
                *(float2*)(Cg + (size_t)(rA + 8) * HH + cn) = r1;
            }
        }
    }
}

// -------------------- launcher --------------------------------------------
extern "C" void kernel_launch(void* const* d_in, const int* in_sizes, int n_in,
                              void* d_out, int out_size) {
    const float* x   = (const float*)d_in[0];
    const int*   w1q = (const int*)d_in[1];
    const float* w1s = (const float*)d_in[2];
    const int*   w2q = (const int*)d_in[3];
    const float* w2s = (const float*)d_in[4];
    float*       out = (float*)d_out;

    void *pw1t, *pw2t, *pahi, *palo, *prs, *ph;
    cudaGetSymbolAddress(&pw1t, g_w1t);
    cudaGetSymbolAddress(&pw2t, g_w2t);
    cudaGetSymbolAddress(&pahi, g_ahi);
    cudaGetSymbolAddress(&palo, g_alo);
    cudaGetSymbolAddress(&prs,  g_rs);
    cudaGetSymbolAddress(&ph,   g_h);

    dim3 cb(32, 8), cg(HH / 32, HH / 32, EE);
    convw_kernel<<<cg, cb>>>(w1q, (int8_t*)pw1t);
    convw_kernel<<<cg, cb>>>(w2q, (int8_t*)pw2t);

    quant_kernel<<<EE * TT, 128>>>(x, (int8_t*)pahi, (int8_t*)palo,
                                   (float*)prs);

    cudaFuncSetAttribute(imma_gemm,
                         cudaFuncAttributeMaxDynamicSharedMemorySize, DYNSMEM);
    dim3 gg(HH / BN, TT / BM, EE);   // (32, 32, 8)

    imma_gemm<<<gg, 256, DYNSMEM>>>((const int8_t*)pahi, (const int8_t*)palo,
                                    (const float*)prs, (const int8_t*)pw1t,
                                    w1s, (float*)ph);

    quant_kernel<<<EE * TT, 128>>>((const float*)ph, (int8_t*)pahi,
                                   (int8_t*)palo, (float*)prs);

    imma_gemm<<<gg, 256, DYNSMEM>>>((const int8_t*)pahi, (const int8_t*)palo,
                                    (const float*)prs, (const int8_t*)pw2t,
                                    w2s, out);
}